// round 11
// baseline (speedup 1.0000x reference)
#include <cuda_runtime.h>
#include <cuda_bf16.h>
#include <math.h>
#include <stdint.h>

// Problem constants
#define LL 6
#define HH 8
#define CC 512
#define DD 64
#define FF 2048
#define VV 32000
#define BB 2
#define TT 1024
#define M2 (BB*TT)          // 2048 token rows
#define BH (BB*HH)          // 16 attention batches
#define QSZ (BH*TT*DD)      // one of Q/K/V

// ---------------------------------------------------------------------------
// Scratch (static device globals — allocation-free per harness rules)
// ---------------------------------------------------------------------------
__device__ float g_enc[M2*CC];
__device__ float g_dec[M2*CC];
__device__ float g_qkv[3*QSZ];           // [j][b][h][T][D]
__device__ float g_s  [(long)BH*TT*TT];  // attention scores (64 MB)
__device__ float g_att[M2*CC];
__device__ float g_ffn[M2*FF];
// bf16 hi/lo plane buffers (hi at +0, lo at +planeOff elements)
__device__ __align__(16) __nv_bfloat16 g_glp[2*M2*CC];        // LN output planes
__device__ __align__(16) __nv_bfloat16 g_gfp[2*(long)M2*FF];  // FFN hidden planes
__device__ __align__(16) __nv_bfloat16 g_gxp[2*M2*CC];        // enc residual planes
__device__ __align__(16) __nv_bfloat16 g_gyp[2*M2*CC];        // dec residual planes

// ---------------------------------------------------------------------------
// bf16x2 double-bf16 helpers: v = hi + lo. 3 bf16 MMAs ~ fp32-ish.
// ---------------------------------------------------------------------------
__device__ __forceinline__ uint32_t pk(float k0, float k1){
    // pack: low half = bf16(k0), high half = bf16(k1)
    uint32_t r; asm("cvt.rn.bf16x2.f32 %0, %1, %2;" : "=r"(r) : "f"(k1), "f"(k0));
    return r;
}
__device__ __forceinline__ float lowf (uint32_t u){ return __uint_as_float(u << 16); }
__device__ __forceinline__ float highf(uint32_t u){ return __uint_as_float(u & 0xffff0000u); }
__device__ __forceinline__ void split4(const float4& v, uint2& hi, uint2& lo){
    uint32_t h0 = pk(v.x, v.y), h1 = pk(v.z, v.w);
    lo = make_uint2(pk(v.x-lowf(h0), v.y-highf(h0)), pk(v.z-lowf(h1), v.w-highf(h1)));
    hi = make_uint2(h0, h1);
}
__device__ __forceinline__ void mma16(float* c, const uint32_t* a, const uint32_t* b){
    asm volatile("mma.sync.aligned.m16n8k16.row.col.f32.bf16.bf16.f32 "
        "{%0,%1,%2,%3},{%4,%5,%6,%7},{%8,%9},{%0,%1,%2,%3};"
        : "+f"(c[0]),"+f"(c[1]),"+f"(c[2]),"+f"(c[3])
        : "r"(a[0]),"r"(a[1]),"r"(a[2]),"r"(a[3]),"r"(b[0]),"r"(b[1]));
}
__device__ __forceinline__ void ldsm4(uint32_t* r, uint32_t addr){
    asm volatile("ldmatrix.sync.aligned.m8n8.x4.shared.b16 {%0,%1,%2,%3}, [%4];"
        : "=r"(r[0]),"=r"(r[1]),"=r"(r[2]),"=r"(r[3]) : "r"(addr));
}
__device__ __forceinline__ void ldsm4t(uint32_t* r, uint32_t addr){
    asm volatile("ldmatrix.sync.aligned.m8n8.x4.trans.shared.b16 {%0,%1,%2,%3}, [%4];"
        : "=r"(r[0]),"=r"(r[1]),"=r"(r[2]),"=r"(r[3]) : "r"(addr));
}

// ---------------------------------------------------------------------------
// Generic batched bf16x2 GEMM, ldmatrix fragment loads, plane smem layout.
// Tile 128x64, BK=32, 8 warps (warp tile 32x32), 2 CTAs/SM.
// CMODE: 0=dense, 1=causal-QK (skip masked tiles), 2=causal-PV (K truncate)
// ASRC:  0=A fp32 (split at STS), 1=A pre-split bf16 planes (pure copy)
// EMIT:  1=epilogue also writes hi/lo bf16 planes of the output
// ---------------------------------------------------------------------------
template<int BM,int BN,int BK,int WM,int WN,bool TRANSB,int CMODE,int ASRC,int EMIT>
__global__ __launch_bounds__(256,2)
void mma_gemm(const float* __restrict__ A, const float* __restrict__ A2,
              const float* __restrict__ B, float* __restrict__ C,
              __nv_bfloat16* __restrict__ Ehi, long aPOff, long ePOff,
              const float* __restrict__ bias, const float* __restrict__ resid,
              int K, int lda, int ldb, int ldc,
              int zDiv1, int zDiv2,
              long aS0, long aS1, long aS2,
              long bS0, long bS1, long bS2,
              long cS0, long cS1, long cS2,
              long sS0, long sS1, long sS2,
              float alpha, int relu)
{
    constexpr int BKA = BK + 8;                 // A plane row stride (elems)
    constexpr int BNB = BN + 8;                 // B plane row stride (elems)
    constexpr int A_PLANE = BM*BKA*2;           // bytes
    constexpr int A_BUF   = 2*A_PLANE;
    constexpr int B_PLANE = BK*BNB*2;
    constexpr int B_BUF   = 2*B_PLANE;
    constexpr int BUF     = A_BUF + B_BUF;
    constexpr int WCOLS = BN / WN;
    constexpr int MITER = WM/16, NITER = WN/8;
    constexpr int AREG = BM*BK/(256*4);

    const int row0 = blockIdx.y * BM;
    const int col0 = blockIdx.x * BN;
    if (CMODE == 1 && col0 > row0 + BM - 1) return;   // fully-masked causal tile
    const int Keff = (CMODE == 2) ? min(K, row0 + BM) : K;

    extern __shared__ char smem[];
    const uint32_t sbase = (uint32_t)__cvta_generic_to_shared(smem);

    const int z = blockIdx.z;
    const int i0 = z / zDiv1, rem = z % zDiv1;
    const int i1 = rem / zDiv2, i2 = rem % zDiv2;
    const float* Asel = (i0==0) ? A : A2;
    const float* Ap = nullptr;
    const __nv_bfloat16* Ahp = nullptr;
    if (ASRC == 0) Ap  = Asel + i0*aS0 + i1*aS1 + i2*aS2;
    else           Ahp = reinterpret_cast<const __nv_bfloat16*>(Asel) + i0*aS0 + i1*aS1 + i2*aS2;
    const float* Bp = B + i0*bS0 + i1*bS1 + i2*bS2;
    const long cOff = i0*cS0 + i1*cS1 + i2*cS2;
    float* Cp = C + cOff;
    const float* Rp = resid ? resid + cOff : nullptr;
    const float* bp = bias ? bias + i0*sS0 + i1*sS1 + i2*sS2 : nullptr;
    __nv_bfloat16* Ep = EMIT ? (Ehi + cOff) : nullptr;

    const int tid  = threadIdx.x;
    const int lane = tid & 31, w = tid >> 5;
    const int wr = w / WCOLS, wc = w % WCOLS;
    const int g  = lane >> 2, cq = lane & 3;

    const int aRow = (lane & 7) + ((lane >> 3) & 1) * 8;
    const int aCol = (lane >> 4) * 8;
    const uint32_t aOffB = ((wr*WM + aRow)*BKA + aCol) * 2;
    const int bRow = lane & 15;
    const int bColOff = (lane >> 4) * 8;
    const uint32_t bOffB = (bRow*BNB + wc*WN + bColOff) * 2;

    float acc[MITER][NITER][4];
    #pragma unroll
    for (int mi=0;mi<MITER;mi++)
        #pragma unroll
        for (int ni=0;ni<NITER;ni++)
            #pragma unroll
            for (int q=0;q<4;q++) acc[mi][ni][q] = 0.f;

    float4 ra[ASRC==0 ? AREG : 1];
    uint4  ra4[ASRC==1 ? 4 : 1];
    float4 rb[2];

    auto ldgA = [&](int k0){
        if (ASRC == 0){
            #pragma unroll
            for (int i=0;i<AREG;i++){
                int id = tid + i*256;
                int r = id >> 3, c4 = id & 7;
                ra[i] = *(const float4*)(Ap + (long)(row0+r)*lda + k0 + c4*4);
            }
        } else {
            #pragma unroll
            for (int i=0;i<2;i++){
                int id = tid + i*256;              // 0..511
                int r = id >> 2, c8 = (id & 3)*8;
                const __nv_bfloat16* hp = Ahp + (long)(row0+r)*lda + k0 + c8;
                ra4[i]   = *(const uint4*)hp;
                ra4[2+i] = *(const uint4*)(hp + aPOff);
            }
        }
    };
    auto stsA = [&](int buf){
        char* base = smem + buf*BUF;
        if (ASRC == 0){
            #pragma unroll
            for (int i=0;i<AREG;i++){
                int id = tid + i*256;
                int r = id >> 3, c4 = id & 7;
                uint2 hi, lo; split4(ra[i], hi, lo);
                int off = (r*BKA + c4*4)*2;
                *(uint2*)(base + off)           = hi;
                *(uint2*)(base + A_PLANE + off) = lo;
            }
        } else {
            #pragma unroll
            for (int i=0;i<2;i++){
                int id = tid + i*256;
                int r = id >> 2, c8 = (id & 3)*8;
                int off = (r*BKA + c8)*2;
                *(uint4*)(base + off)           = ra4[i];
                *(uint4*)(base + A_PLANE + off) = ra4[2+i];
            }
        }
    };
    auto ldgB = [&](int k0){
        #pragma unroll
        for (int j=0;j<2;j++){
            int id = tid + j*256;
            if (!TRANSB){
                int r = id >> 4, n4 = id & 15;
                rb[j] = *(const float4*)(Bp + (long)(k0+r)*ldb + col0 + n4*4);
            } else {
                int n = id >> 3, kg = id & 7;
                rb[j] = *(const float4*)(Bp + (long)(col0+n)*ldb + k0 + kg*4);
            }
        }
    };
    auto stsB = [&](int buf){
        char* base = smem + buf*BUF + A_BUF;
        #pragma unroll
        for (int j=0;j<2;j++){
            int id = tid + j*256;
            if (!TRANSB){
                int r = id >> 4, n4 = id & 15;
                uint2 hi, lo; split4(rb[j], hi, lo);
                int off = (r*BNB + n4*4)*2;
                *(uint2*)(base + off)           = hi;
                *(uint2*)(base + B_PLANE + off) = lo;
            } else {
                int n = id >> 3, kg = id & 7;
                float v[4] = {rb[j].x, rb[j].y, rb[j].z, rb[j].w};
                #pragma unroll
                for (int e=0;e<4;e++){
                    int k = kg*4 + e;
                    uint32_t h = pk(v[e], 0.f);
                    float hf = __uint_as_float(h << 16);
                    uint32_t l = pk(v[e]-hf, 0.f);
                    int off = (k*BNB + n)*2;
                    *(uint16_t*)(base + off)           = (uint16_t)h;
                    *(uint16_t*)(base + B_PLANE + off) = (uint16_t)l;
                }
            }
        }
    };
    auto compute = [&](int buf){
        const uint32_t aAddr = sbase + buf*BUF + aOffB;
        const uint32_t bAddr = sbase + buf*BUF + A_BUF + bOffB;
        #pragma unroll
        for (int s=0; s<BK/16; s++){
            uint32_t ah[MITER][4], al[MITER][4];
            #pragma unroll
            for (int mi=0; mi<MITER; mi++){
                uint32_t a = aAddr + (mi*16*BKA + s*16)*2;
                ldsm4(ah[mi], a);
                ldsm4(al[mi], a + A_PLANE);
            }
            uint32_t bh[2][4], bl[2][4];
            #pragma unroll
            for (int np=0; np<NITER/2; np++){
                uint32_t b = bAddr + (s*16*BNB + np*16)*2;
                ldsm4t(bh[np], b);
                ldsm4t(bl[np], b + B_PLANE);
            }
            #pragma unroll
            for (int mi=0; mi<MITER; mi++)
                #pragma unroll
                for (int ni=0; ni<NITER; ni++){
                    const uint32_t* bhp = &bh[ni>>1][(ni&1)*2];
                    const uint32_t* blp = &bl[ni>>1][(ni&1)*2];
                    mma16(acc[mi][ni], al[mi], bhp);
                    mma16(acc[mi][ni], ah[mi], blp);
                    mma16(acc[mi][ni], ah[mi], bhp);
                }
        }
    };

    const int nIter = Keff/BK;
    ldgA(0); ldgB(0);
    stsA(0); stsB(0);
    __syncthreads();
    for (int it=0; it<nIter; ++it){
        if (it+1 < nIter){ ldgA((it+1)*BK); ldgB((it+1)*BK); }
        compute(it & 1);
        if (it+1 < nIter){ stsA((it+1)&1); stsB((it+1)&1); }
        __syncthreads();
    }

    #pragma unroll
    for (int mi=0;mi<MITER;mi++){
        #pragma unroll
        for (int ni=0;ni<NITER;ni++){
            int r  = row0 + wr*WM + mi*16 + g;
            int cl = col0 + wc*WN + ni*8 + 2*cq;
            #pragma unroll
            for (int h=0; h<2; h++){
                int rr = r + 8*h;
                float x = acc[mi][ni][2*h  ]*alpha;
                float y = acc[mi][ni][2*h+1]*alpha;
                if (bp){ x += bp[cl]; y += bp[cl+1]; }
                if (Rp){ float2 t = *(const float2*)(Rp + (long)rr*ldc + cl);
                         x += t.x; y += t.y; }
                if (relu){ x = fmaxf(x,0.f); y = fmaxf(y,0.f); }
                *(float2*)(Cp + (long)rr*ldc + cl) = make_float2(x,y);
                if (EMIT){
                    uint32_t hh = pk(x,y);
                    uint32_t ll = pk(x-lowf(hh), y-highf(hh));
                    *(uint32_t*)(Ep + (long)rr*ldc + cl)        = hh;
                    *(uint32_t*)(Ep + ePOff + (long)rr*ldc + cl) = ll;
                }
            }
        }
    }
}

template<int BM,int BN,int BK>
constexpr int smemBytes(){
    return 2 * ( 2*BM*(BK+8)*2 + 2*BK*(BN+8)*2 );
}

// ---------------------------------------------------------------------------
// Block reductions (256 threads)
// ---------------------------------------------------------------------------
template<bool IS_MAX>
__device__ __forceinline__ float blockReduce(float v)
{
    __shared__ float sh[8];
    int lane = threadIdx.x & 31, w = threadIdx.x >> 5;
    #pragma unroll
    for (int o=16;o;o>>=1) {
        float u = __shfl_xor_sync(0xffffffffu, v, o);
        v = IS_MAX ? fmaxf(v,u) : v+u;
    }
    if (lane==0) sh[w] = v;
    __syncthreads();
    if (w==0) {
        v = (lane < 8) ? sh[lane] : (IS_MAX ? -__int_as_float(0x7f800000) : 0.f);
        #pragma unroll
        for (int o=4;o;o>>=1) {
            float u = __shfl_xor_sync(0xffffffffu, v, o);
            v = IS_MAX ? fmaxf(v,u) : v+u;
        }
        if (lane==0) sh[0] = v;
    }
    __syncthreads();
    float r = sh[0];
    __syncthreads();
    return r;
}

// ---------------------------------------------------------------------------
// Single-pass softmax: row of T=1024 in registers (float4/thread).
// Writes exact zeros in the causal-masked region (PV truncation relies on it).
// ---------------------------------------------------------------------------
__global__ __launch_bounds__(256)
void softmax_k(float* __restrict__ s, int causal)
{
    long row = blockIdx.x;
    int t = (int)(row % TT);
    float4* p = (float4*)(s + row * (long)TT);
    int tid = threadIdx.x;
    int base = 4*tid;
    int n = causal ? (t+1) : TT;

    float4 v = p[tid];
    const float NEG = -__int_as_float(0x7f800000);
    if (base+0 >= n) v.x = NEG;
    if (base+1 >= n) v.y = NEG;
    if (base+2 >= n) v.z = NEG;
    if (base+3 >= n) v.w = NEG;

    float mx = fmaxf(fmaxf(v.x,v.y), fmaxf(v.z,v.w));
    mx = blockReduce<true>(mx);

    float4 e;
    e.x = __expf(v.x - mx); e.y = __expf(v.y - mx);
    e.z = __expf(v.z - mx); e.w = __expf(v.w - mx);
    float sum = (e.x + e.y) + (e.z + e.w);
    sum = blockReduce<false>(sum);
    float inv = 1.f / sum;
    e.x *= inv; e.y *= inv; e.z *= inv; e.w *= inv;
    p[tid] = e;
}

// ---------------------------------------------------------------------------
// LayerNorm: rows of C=512 -> hi/lo bf16 planes (consumed only as GEMM A)
// ---------------------------------------------------------------------------
__global__ __launch_bounds__(256)
void ln_k(const float* __restrict__ x,
          __nv_bfloat16* __restrict__ outH, __nv_bfloat16* __restrict__ outL,
          const float* __restrict__ gamma, const float* __restrict__ beta)
{
    long row = blockIdx.x;
    const float* xr = x + row*(long)CC;
    int tid = threadIdx.x;
    float v0 = xr[tid], v1 = xr[tid+256];
    float mu = blockReduce<false>(v0+v1) * (1.f/CC);
    float d0 = v0-mu, d1 = v1-mu;
    float var = blockReduce<false>(d0*d0 + d1*d1) * (1.f/CC);
    float inv = rsqrtf(var + 1e-5f);
    float r0 = d0*inv*gamma[tid]     + beta[tid];
    float r1 = d1*inv*gamma[tid+256] + beta[tid+256];
    __nv_bfloat16 h0 = __float2bfloat16(r0);
    __nv_bfloat16 h1 = __float2bfloat16(r1);
    long o = row*(long)CC;
    outH[o + tid      ] = h0;
    outH[o + tid + 256] = h1;
    outL[o + tid      ] = __float2bfloat16(r0 - __bfloat162float(h0));
    outL[o + tid + 256] = __float2bfloat16(r1 - __bfloat162float(h1));
}

// ---------------------------------------------------------------------------
// Embedding + positional encoding
// ---------------------------------------------------------------------------
__global__ __launch_bounds__(256)
void embed_k(const int* __restrict__ tok, const float* __restrict__ emb,
             float* __restrict__ out)
{
    long idx = (long)blockIdx.x*256 + threadIdx.x;
    if (idx >= (long)BB*TT*CC) return;
    int c = (int)(idx % CC);
    long bt = idx / CC;
    int t = (int)(bt % TT);
    int token = tok[bt];
    const int half = CC/2;
    float pe;
    if (c < half) {
        float rate = powf(10000.f, -(float)c / half);
        pe = sinf((float)t * rate);
    } else {
        float rate = powf(10000.f, -(float)(c-half) / half);
        pe = cosf((float)t * rate);
    }
    out[idx] = emb[(long)token*CC + c] * 22.62741699796952f + pe;  // sqrt(512)
}

// ---------------------------------------------------------------------------
// Host-side launchers
// ---------------------------------------------------------------------------
#define GEMM_D0 mma_gemm<128,64,32,32,32,false,0,0,0>
#define GEMM_D2 mma_gemm<128,64,32,32,32,false,2,0,0>
#define GEMM_T0 mma_gemm<128,64,32,32,32,true ,0,0,0>
#define GEMM_T1 mma_gemm<128,64,32,32,32,true ,1,0,0>
#define GEMM_P0 mma_gemm<128,64,32,32,32,false,0,1,0>
#define GEMM_P1 mma_gemm<128,64,32,32,32,false,0,1,1>

static void setAttrs()
{
    int sb = smemBytes<128,64,32>();
    cudaFuncSetAttribute((const void*)GEMM_D0, cudaFuncAttributeMaxDynamicSharedMemorySize, sb);
    cudaFuncSetAttribute((const void*)GEMM_D2, cudaFuncAttributeMaxDynamicSharedMemorySize, sb);
    cudaFuncSetAttribute((const void*)GEMM_T0, cudaFuncAttributeMaxDynamicSharedMemorySize, sb);
    cudaFuncSetAttribute((const void*)GEMM_T1, cudaFuncAttributeMaxDynamicSharedMemorySize, sb);
    cudaFuncSetAttribute((const void*)GEMM_P0, cudaFuncAttributeMaxDynamicSharedMemorySize, sb);
    cudaFuncSetAttribute((const void*)GEMM_P1, cudaFuncAttributeMaxDynamicSharedMemorySize, sb);
}

// fp32-A dense GEMM (old path): used for attention-out projections
static void gemmP(const float* A, const float* B, float* C,
                  const float* bias, const float* resid,
                  int M, int N, int K, int relu)
{
    dim3 g(N/64, M/128, 1);
    GEMM_D0<<<g,256,smemBytes<128,64,32>()>>>(
        A, A, B, C, nullptr, 0, 0, bias, resid, K, K, N, N,
        1,1, 0,0,0, 0,0,0, 0,0,0, 0,0,0, 1.f, relu);
}

// plane-A dense GEMM; optional plane emission
static void gemmPA(const __nv_bfloat16* Ahi, long aPOff,
                   const float* B, float* C,
                   __nv_bfloat16* Ehi, long ePOff,
                   const float* bias, const float* resid,
                   int M, int N, int K, int relu)
{
    dim3 g(N/64, M/128, 1);
    if (Ehi)
        GEMM_P1<<<g,256,smemBytes<128,64,32>()>>>(
            (const float*)Ahi, (const float*)Ahi, B, C, Ehi, aPOff, ePOff,
            bias, resid, K, K, N, N,
            1,1, 0,0,0, 0,0,0, 0,0,0, 0,0,0, 1.f, relu);
    else
        GEMM_P0<<<g,256,smemBytes<128,64,32>()>>>(
            (const float*)Ahi, (const float*)Ahi, B, C, nullptr, aPOff, 0,
            bias, resid, K, K, N, N,
            1,1, 0,0,0, 0,0,0, 0,0,0, 0,0,0, 1.f, relu);
}

// Full multi-head attention; att gets head-concat output [B*T, C].
// xqP/xkvP are bf16 plane buffers (hi base; lo at +M2*CC).
static void attention(const __nv_bfloat16* xqP, const __nv_bfloat16* xkvP,
                      const float* wqkv, const float* bqkv,
                      float* qkv, float* s, float* att, int causal)
{
    const int sb = smemBytes<128,64,32>();
    // Fused QKV projection: z = j*16 + b*8 + h   (j selects A vs A2); A planes
    {
        dim3 g(1, TT/128, 48);
        GEMM_P0<<<g,256,sb>>>(
            (const float*)xqP, (const float*)xkvP, wqkv, qkv,
            nullptr, (long)M2*CC, 0,
            bqkv, nullptr,
            CC, CC, DD, DD,
            16, 8,
            0, (long)TT*CC, 0,
            (long)HH*CC*DD, 0, (long)CC*DD,
            (long)QSZ, (long)HH*TT*DD, (long)TT*DD,
            (long)HH*DD, 0, (long)DD,
            1.f, 0);
    }
    // scores = Q @ K^T * sqrt(D)   (z = b*H+h)
    {
        dim3 g(TT/64, TT/128, BH);
        if (causal)
            GEMM_T1<<<g,256,sb>>>(
                qkv, qkv, qkv + QSZ, s, nullptr, 0, 0, nullptr, nullptr,
                DD, DD, DD, TT,
                1000000, 1,
                0, (long)TT*DD, 0,
                0, (long)TT*DD, 0,
                0, (long)TT*TT, 0,
                0,0,0,
                8.0f, 0);
        else
            GEMM_T0<<<g,256,sb>>>(
                qkv, qkv, qkv + QSZ, s, nullptr, 0, 0, nullptr, nullptr,
                DD, DD, DD, TT,
                1000000, 1,
                0, (long)TT*DD, 0,
                0, (long)TT*DD, 0,
                0, (long)TT*TT, 0,
                0,0,0,
                8.0f, 0);
    }
    softmax_k<<<BH*TT, 256>>>(s, causal);
    // out = P @ V, written at head-concat position (ldc = C, col offset h*D)
    {
        dim3 g(1, TT/128, BH);
        if (causal)
            GEMM_D2<<<g,256,sb>>>(
                s, s, qkv + 2*QSZ, att, nullptr, 0, 0, nullptr, nullptr,
                TT, TT, DD, CC,
                1000000, HH,
                0, (long)HH*TT*TT, (long)TT*TT,
                0, (long)HH*TT*DD, (long)TT*DD,
                0, (long)TT*CC, (long)DD,
                0,0,0,
                1.f, 0);
        else
            GEMM_D0<<<g,256,sb>>>(
                s, s, qkv + 2*QSZ, att, nullptr, 0, 0, nullptr, nullptr,
                TT, TT, DD, CC,
                1000000, HH,
                0, (long)HH*TT*TT, (long)TT*TT,
                0, (long)HH*TT*DD, (long)TT*DD,
                0, (long)TT*CC, (long)DD,
                0,0,0,
                1.f, 0);
    }
}

extern "C" void kernel_launch(void* const* d_in, const int* in_sizes, int n_in,
                              void* d_out, int out_size)
{
    const int*   src     = (const int*)  d_in[0];
    const int*   tgt     = (const int*)  d_in[1];
    const float* src_emb = (const float*)d_in[2];
    const float* tgt_emb = (const float*)d_in[3];
    const float* e_wqkv  = (const float*)d_in[4];
    const float* e_bqkv  = (const float*)d_in[5];
    const float* e_wo    = (const float*)d_in[6];
    const float* e_bo    = (const float*)d_in[7];
    const float* e_ln1   = (const float*)d_in[8];
    const float* e_ln2   = (const float*)d_in[9];
    const float* e_fw1   = (const float*)d_in[10];
    const float* e_fb1   = (const float*)d_in[11];
    const float* e_fw2   = (const float*)d_in[12];
    const float* e_fb2   = (const float*)d_in[13];
    const float* dsw     = (const float*)d_in[14];
    const float* dsb     = (const float*)d_in[15];
    const float* dw1     = (const float*)d_in[16];
    const float* db1     = (const float*)d_in[17];
    const float* dln1    = (const float*)d_in[18];
    const float* dcw     = (const float*)d_in[19];
    const float* dcb     = (const float*)d_in[20];
    const float* dw2     = (const float*)d_in[21];
    const float* db2     = (const float*)d_in[22];
    const float* dln2    = (const float*)d_in[23];
    const float* dln3    = (const float*)d_in[24];
    const float* dfw1    = (const float*)d_in[25];
    const float* dfb1    = (const float*)d_in[26];
    const float* dfw2    = (const float*)d_in[27];
    const float* dfb2    = (const float*)d_in[28];
    const float* wf      = (const float*)d_in[29];
    const float* bf      = (const float*)d_in[30];
    float* out = (float*)d_out;

    setAttrs();

    float *gx,*gy,*gq,*gs,*ga,*gf;
    __nv_bfloat16 *glp,*gfp,*gxp,*gyp;
    cudaGetSymbolAddress((void**)&gx, g_enc);
    cudaGetSymbolAddress((void**)&gy, g_dec);
    cudaGetSymbolAddress((void**)&gq, g_qkv);
    cudaGetSymbolAddress((void**)&gs, g_s);
    cudaGetSymbolAddress((void**)&ga, g_att);
    cudaGetSymbolAddress((void**)&gf, g_ffn);
    cudaGetSymbolAddress((void**)&glp, g_glp);
    cudaGetSymbolAddress((void**)&gfp, g_gfp);
    cudaGetSymbolAddress((void**)&gxp, g_gxp);
    cudaGetSymbolAddress((void**)&gyp, g_gyp);

    const long PO_C = (long)M2*CC;   // plane offset for [M2,C] buffers
    const long PO_F = (long)M2*FF;   // plane offset for [M2,F] buffer
    const int embBlocks = (int)(((long)BB*TT*CC + 255) / 256);

    // ---------------- Encoder ----------------
    embed_k<<<embBlocks,256>>>(src, src_emb, gx);
    for (int l=0; l<LL; l++) {
        const float* ln1g = e_ln1 + (long)l*2*CC;
        ln_k<<<M2,256>>>(gx, glp, glp + PO_C, ln1g, ln1g + CC);
        attention(glp, glp,
                  e_wqkv + (long)l*3*HH*CC*DD, e_bqkv + (long)l*3*HH*DD,
                  gq, gs, ga, 0);
        gemmP(ga, e_wo + (long)l*CC*CC, gx, e_bo + (long)l*CC, gx, M2, CC, CC, 0);
        const float* ln2g = e_ln2 + (long)l*2*CC;
        ln_k<<<M2,256>>>(gx, glp, glp + PO_C, ln2g, ln2g + CC);
        gemmPA(glp, PO_C, e_fw1 + (long)l*CC*FF, gf, gfp, PO_F,
               e_fb1 + (long)l*FF, nullptr, M2, FF, CC, 1);
        gemmPA(gfp, PO_F, e_fw2 + (long)l*FF*CC, gx, gxp, PO_C,
               e_fb2 + (long)l*CC, gx, M2, CC, FF, 0);
    }

    // ---------------- Decoder ----------------
    embed_k<<<embBlocks,256>>>(tgt, tgt_emb, gy);
    for (int l=0; l<LL; l++) {
        const float* l1 = dln1 + (long)l*2*CC;
        ln_k<<<M2,256>>>(gy, glp, glp + PO_C, l1, l1 + CC);
        attention(glp, glp,
                  dsw + (long)l*3*HH*CC*DD, dsb + (long)l*3*HH*DD,
                  gq, gs, ga, 1);                      // causal
        gemmP(ga, dw1 + (long)l*CC*CC, gy, db1 + (long)l*CC, gy, M2, CC, CC, 0);
        const float* l2 = dln2 + (long)l*2*CC;
        ln_k<<<M2,256>>>(gy, glp, glp + PO_C, l2, l2 + CC);
        attention(glp, gxp,                            // cross: kv = enc_out planes
                  dcw + (long)l*3*HH*CC*DD, dcb + (long)l*3*HH*DD,
                  gq, gs, ga, 0);
        gemmP(ga, dw2 + (long)l*CC*CC, gy, db2 + (long)l*CC, gy, M2, CC, CC, 0);
        const float* l3 = dln3 + (long)l*2*CC;
        ln_k<<<M2,256>>>(gy, glp, glp + PO_C, l3, l3 + CC);
        gemmPA(glp, PO_C, dfw1 + (long)l*CC*FF, gf, gfp, PO_F,
               dfb1 + (long)l*FF, nullptr, M2, FF, CC, 1);
        gemmPA(gfp, PO_F, dfw2 + (long)l*FF*CC, gy, gyp, PO_C,
               dfb2 + (long)l*CC, gy, M2, CC, FF, 0);
    }

    // ---------------- Final logits ----------------
    gemmPA(gyp, PO_C, wf, out, nullptr, 0, bf, nullptr, M2, VV, CC, 0);
}

// round 12
// speedup vs baseline: 1.0476x; 1.0476x over previous
#include <cuda_runtime.h>
#include <cuda_bf16.h>
#include <math.h>
#include <stdint.h>

// Problem constants
#define LL 6
#define HH 8
#define CC 512
#define DD 64
#define FF 2048
#define VV 32000
#define BB 2
#define TT 1024
#define M2 (BB*TT)          // 2048 token rows
#define BH (BB*HH)          // 16 attention batches
#define QSZ (BH*TT*DD)      // one of Q/K/V

// ---------------------------------------------------------------------------
// Scratch (static device globals — allocation-free per harness rules)
// ---------------------------------------------------------------------------
__device__ float g_enc[M2*CC];
__device__ float g_dec[M2*CC];
__device__ float g_ln [M2*CC];
__device__ float g_s  [(long)BH*TT*TT];  // attention scores (64 MB)
__device__ float g_att[M2*CC];
__device__ float g_ffn[M2*FF];
// QKV bf16 hi/lo planes: [hi: j,b,h,T,D][lo: same], lo at +3*QSZ elements
__device__ __align__(16) __nv_bfloat16 g_qkvp[2*3*QSZ];

// ---------------------------------------------------------------------------
// bf16x2 double-bf16 helpers: v = hi + lo. 3 bf16 MMAs ~ fp32-ish.
// ---------------------------------------------------------------------------
__device__ __forceinline__ uint32_t pk(float k0, float k1){
    // pack: low half = bf16(k0), high half = bf16(k1)
    uint32_t r; asm("cvt.rn.bf16x2.f32 %0, %1, %2;" : "=r"(r) : "f"(k1), "f"(k0));
    return r;
}
__device__ __forceinline__ float lowf (uint32_t u){ return __uint_as_float(u << 16); }
__device__ __forceinline__ float highf(uint32_t u){ return __uint_as_float(u & 0xffff0000u); }
__device__ __forceinline__ void split4(const float4& v, uint2& hi, uint2& lo){
    uint32_t h0 = pk(v.x, v.y), h1 = pk(v.z, v.w);
    lo = make_uint2(pk(v.x-lowf(h0), v.y-highf(h0)), pk(v.z-lowf(h1), v.w-highf(h1)));
    hi = make_uint2(h0, h1);
}
__device__ __forceinline__ void mma16(float* c, const uint32_t* a, const uint32_t* b){
    asm volatile("mma.sync.aligned.m16n8k16.row.col.f32.bf16.bf16.f32 "
        "{%0,%1,%2,%3},{%4,%5,%6,%7},{%8,%9},{%0,%1,%2,%3};"
        : "+f"(c[0]),"+f"(c[1]),"+f"(c[2]),"+f"(c[3])
        : "r"(a[0]),"r"(a[1]),"r"(a[2]),"r"(a[3]),"r"(b[0]),"r"(b[1]));
}
__device__ __forceinline__ void ldsm4(uint32_t* r, uint32_t addr){
    asm volatile("ldmatrix.sync.aligned.m8n8.x4.shared.b16 {%0,%1,%2,%3}, [%4];"
        : "=r"(r[0]),"=r"(r[1]),"=r"(r[2]),"=r"(r[3]) : "r"(addr));
}
__device__ __forceinline__ void ldsm4t(uint32_t* r, uint32_t addr){
    asm volatile("ldmatrix.sync.aligned.m8n8.x4.trans.shared.b16 {%0,%1,%2,%3}, [%4];"
        : "=r"(r[0]),"=r"(r[1]),"=r"(r[2]),"=r"(r[3]) : "r"(addr));
}

// ---------------------------------------------------------------------------
// Generic batched bf16x2 GEMM, ldmatrix fragment loads, plane smem layout.
// Tile 128x64, BK=32, 8 warps (warp tile 32x32), 2 CTAs/SM.
// CMODE: 0=dense, 1=causal-QK (skip masked tiles), 2=causal-PV (K truncate)
// ASRC:  0=A fp32 (split at STS), 1=A pre-split bf16 planes (pure copy)
// BSRC:  0=B fp32 (split at STS), 1=B pre-split bf16 planes (pure copy)
// EMIT:  0=write fp32 C, 2=write bf16 hi/lo planes ONLY (no fp32)
// ---------------------------------------------------------------------------
template<int BM,int BN,int BK,int WM,int WN,bool TRANSB,int CMODE,int ASRC,int BSRC,int EMIT>
__global__ __launch_bounds__(256,2)
void mma_gemm(const float* __restrict__ A, const float* __restrict__ A2,
              const float* __restrict__ B, float* __restrict__ C,
              __nv_bfloat16* __restrict__ Ehi, long aPOff, long bPOff, long ePOff,
              const float* __restrict__ bias, const float* __restrict__ resid,
              int K, int lda, int ldb, int ldc,
              int zDiv1, int zDiv2,
              long aS0, long aS1, long aS2,
              long bS0, long bS1, long bS2,
              long cS0, long cS1, long cS2,
              long sS0, long sS1, long sS2,
              float alpha, int relu)
{
    constexpr int BKA = BK + 8;                 // A plane row stride (elems)
    constexpr int BNB = BN + 8;                 // B plane row stride (elems)
    constexpr int A_PLANE = BM*BKA*2;           // bytes
    constexpr int A_BUF   = 2*A_PLANE;
    constexpr int B_PLANE = BK*BNB*2;
    constexpr int B_BUF   = 2*B_PLANE;
    constexpr int BUF     = A_BUF + B_BUF;
    constexpr int WCOLS = BN / WN;
    constexpr int MITER = WM/16, NITER = WN/8;
    constexpr int AREG = BM*BK/(256*4);

    const int row0 = blockIdx.y * BM;
    const int col0 = blockIdx.x * BN;
    if (CMODE == 1 && col0 > row0 + BM - 1) return;   // fully-masked causal tile
    const int Keff = (CMODE == 2) ? min(K, row0 + BM) : K;

    extern __shared__ char smem[];
    const uint32_t sbase = (uint32_t)__cvta_generic_to_shared(smem);

    const int z = blockIdx.z;
    const int i0 = z / zDiv1, rem = z % zDiv1;
    const int i1 = rem / zDiv2, i2 = rem % zDiv2;
    const float* Asel = (i0==0) ? A : A2;
    const float* Ap = nullptr;
    const __nv_bfloat16* Ahp = nullptr;
    if (ASRC == 0) Ap  = Asel + i0*aS0 + i1*aS1 + i2*aS2;
    else           Ahp = reinterpret_cast<const __nv_bfloat16*>(Asel) + i0*aS0 + i1*aS1 + i2*aS2;
    const float* Bp = nullptr;
    const __nv_bfloat16* Bhp = nullptr;
    if (BSRC == 0) Bp  = B + i0*bS0 + i1*bS1 + i2*bS2;
    else           Bhp = reinterpret_cast<const __nv_bfloat16*>(B) + i0*bS0 + i1*bS1 + i2*bS2;
    const long cOff = i0*cS0 + i1*cS1 + i2*cS2;
    float* Cp = C + cOff;
    const float* Rp = resid ? resid + cOff : nullptr;
    const float* bp = bias ? bias + i0*sS0 + i1*sS1 + i2*sS2 : nullptr;
    __nv_bfloat16* Ep = (EMIT==2) ? (Ehi + cOff) : nullptr;

    const int tid  = threadIdx.x;
    const int lane = tid & 31, w = tid >> 5;
    const int wr = w / WCOLS, wc = w % WCOLS;
    const int g  = lane >> 2, cq = lane & 3;

    const int aRow = (lane & 7) + ((lane >> 3) & 1) * 8;
    const int aCol = (lane >> 4) * 8;
    const uint32_t aOffB = ((wr*WM + aRow)*BKA + aCol) * 2;
    const int bRow = lane & 15;
    const int bColOff = (lane >> 4) * 8;
    const uint32_t bOffB = (bRow*BNB + wc*WN + bColOff) * 2;

    float acc[MITER][NITER][4];
    #pragma unroll
    for (int mi=0;mi<MITER;mi++)
        #pragma unroll
        for (int ni=0;ni<NITER;ni++)
            #pragma unroll
            for (int q=0;q<4;q++) acc[mi][ni][q] = 0.f;

    float4 ra[ASRC==0 ? AREG : 1];
    uint4  ra4[ASRC==1 ? 4 : 1];
    float4 rb[BSRC==0 ? 2 : 1];
    uint4  rb4[BSRC==1 ? 2 : 1];

    auto ldgA = [&](int k0){
        if (ASRC == 0){
            #pragma unroll
            for (int i=0;i<AREG;i++){
                int id = tid + i*256;
                int r = id >> 3, c4 = id & 7;
                ra[i] = *(const float4*)(Ap + (long)(row0+r)*lda + k0 + c4*4);
            }
        } else {
            #pragma unroll
            for (int i=0;i<2;i++){
                int id = tid + i*256;              // 0..511
                int r = id >> 2, c8 = (id & 3)*8;
                const __nv_bfloat16* hp = Ahp + (long)(row0+r)*lda + k0 + c8;
                ra4[i]   = *(const uint4*)hp;
                ra4[2+i] = *(const uint4*)(hp + aPOff);
            }
        }
    };
    auto stsA = [&](int buf){
        char* base = smem + buf*BUF;
        if (ASRC == 0){
            #pragma unroll
            for (int i=0;i<AREG;i++){
                int id = tid + i*256;
                int r = id >> 3, c4 = id & 7;
                uint2 hi, lo; split4(ra[i], hi, lo);
                int off = (r*BKA + c4*4)*2;
                *(uint2*)(base + off)           = hi;
                *(uint2*)(base + A_PLANE + off) = lo;
            }
        } else {
            #pragma unroll
            for (int i=0;i<2;i++){
                int id = tid + i*256;
                int r = id >> 2, c8 = (id & 3)*8;
                int off = (r*BKA + c8)*2;
                *(uint4*)(base + off)           = ra4[i];
                *(uint4*)(base + A_PLANE + off) = ra4[2+i];
            }
        }
    };
    auto ldgB = [&](int k0){
        if (BSRC == 0){
            #pragma unroll
            for (int j=0;j<2;j++){
                int id = tid + j*256;
                if (!TRANSB){
                    int r = id >> 4, n4 = id & 15;
                    rb[j] = *(const float4*)(Bp + (long)(k0+r)*ldb + col0 + n4*4);
                } else {
                    int n = id >> 3, kg = id & 7;
                    rb[j] = *(const float4*)(Bp + (long)(col0+n)*ldb + k0 + kg*4);
                }
            }
        } else {
            if (!TRANSB){
                int r = tid >> 3, n8 = (tid & 7)*8;
                const __nv_bfloat16* hp = Bhp + (long)(k0+r)*ldb + col0 + n8;
                rb4[0] = *(const uint4*)hp;
                rb4[1] = *(const uint4*)(hp + bPOff);
            } else {
                int n = tid >> 2, kg = (tid & 3)*8;
                const __nv_bfloat16* hp = Bhp + (long)(col0+n)*ldb + k0 + kg;
                rb4[0] = *(const uint4*)hp;
                rb4[1] = *(const uint4*)(hp + bPOff);
            }
        }
    };
    auto stsB = [&](int buf){
        char* base = smem + buf*BUF + A_BUF;
        if (BSRC == 0){
            #pragma unroll
            for (int j=0;j<2;j++){
                int id = tid + j*256;
                if (!TRANSB){
                    int r = id >> 4, n4 = id & 15;
                    uint2 hi, lo; split4(rb[j], hi, lo);
                    int off = (r*BNB + n4*4)*2;
                    *(uint2*)(base + off)           = hi;
                    *(uint2*)(base + B_PLANE + off) = lo;
                } else {
                    int n = id >> 3, kg = id & 7;
                    float v[4] = {rb[j].x, rb[j].y, rb[j].z, rb[j].w};
                    #pragma unroll
                    for (int e=0;e<4;e++){
                        int k = kg*4 + e;
                        uint32_t h = pk(v[e], 0.f);
                        float hf = __uint_as_float(h << 16);
                        uint32_t l = pk(v[e]-hf, 0.f);
                        int off = (k*BNB + n)*2;
                        *(uint16_t*)(base + off)           = (uint16_t)h;
                        *(uint16_t*)(base + B_PLANE + off) = (uint16_t)l;
                    }
                }
            }
        } else {
            if (!TRANSB){
                int r = tid >> 3, n8 = (tid & 7)*8;
                int off = (r*BNB + n8)*2;
                *(uint4*)(base + off)           = rb4[0];
                *(uint4*)(base + B_PLANE + off) = rb4[1];
            } else {
                int n = tid >> 2, kg = (tid & 3)*8;
                union { uint4 u; uint16_t s[8]; } uh, ul;
                uh.u = rb4[0]; ul.u = rb4[1];
                #pragma unroll
                for (int e=0;e<8;e++){
                    int off = ((kg+e)*BNB + n)*2;
                    *(uint16_t*)(base + off)           = uh.s[e];
                    *(uint16_t*)(base + B_PLANE + off) = ul.s[e];
                }
            }
        }
    };
    auto compute = [&](int buf){
        const uint32_t aAddr = sbase + buf*BUF + aOffB;
        const uint32_t bAddr = sbase + buf*BUF + A_BUF + bOffB;
        #pragma unroll
        for (int s=0; s<BK/16; s++){
            uint32_t ah[MITER][4], al[MITER][4];
            #pragma unroll
            for (int mi=0; mi<MITER; mi++){
                uint32_t a = aAddr + (mi*16*BKA + s*16)*2;
                ldsm4(ah[mi], a);
                ldsm4(al[mi], a + A_PLANE);
            }
            uint32_t bh[2][4], bl[2][4];
            #pragma unroll
            for (int np=0; np<NITER/2; np++){
                uint32_t b = bAddr + (s*16*BNB + np*16)*2;
                ldsm4t(bh[np], b);
                ldsm4t(bl[np], b + B_PLANE);
            }
            #pragma unroll
            for (int mi=0; mi<MITER; mi++)
                #pragma unroll
                for (int ni=0; ni<NITER; ni++){
                    const uint32_t* bhp = &bh[ni>>1][(ni&1)*2];
                    const uint32_t* blp = &bl[ni>>1][(ni&1)*2];
                    mma16(acc[mi][ni], al[mi], bhp);
                    mma16(acc[mi][ni], ah[mi], blp);
                    mma16(acc[mi][ni], ah[mi], bhp);
                }
        }
    };

    const int nIter = Keff/BK;
    ldgA(0); ldgB(0);
    stsA(0); stsB(0);
    __syncthreads();
    for (int it=0; it<nIter; ++it){
        if (it+1 < nIter){ ldgA((it+1)*BK); ldgB((it+1)*BK); }
        compute(it & 1);
        if (it+1 < nIter){ stsA((it+1)&1); stsB((it+1)&1); }
        __syncthreads();
    }

    #pragma unroll
    for (int mi=0;mi<MITER;mi++){
        #pragma unroll
        for (int ni=0;ni<NITER;ni++){
            int r  = row0 + wr*WM + mi*16 + g;
            int cl = col0 + wc*WN + ni*8 + 2*cq;
            #pragma unroll
            for (int h=0; h<2; h++){
                int rr = r + 8*h;
                float x = acc[mi][ni][2*h  ]*alpha;
                float y = acc[mi][ni][2*h+1]*alpha;
                if (bp){ x += bp[cl]; y += bp[cl+1]; }
                if (Rp){ float2 t = *(const float2*)(Rp + (long)rr*ldc + cl);
                         x += t.x; y += t.y; }
                if (relu){ x = fmaxf(x,0.f); y = fmaxf(y,0.f); }
                if (EMIT == 2){
                    uint32_t hh = pk(x,y);
                    uint32_t ll = pk(x-lowf(hh), y-highf(hh));
                    *(uint32_t*)(Ep + (long)rr*ldc + cl)         = hh;
                    *(uint32_t*)(Ep + ePOff + (long)rr*ldc + cl) = ll;
                } else {
                    *(float2*)(Cp + (long)rr*ldc + cl) = make_float2(x,y);
                }
            }
        }
    }
}

template<int BM,int BN,int BK>
constexpr int smemBytes(){
    return 2 * ( 2*BM*(BK+8)*2 + 2*BK*(BN+8)*2 );
}

// ---------------------------------------------------------------------------
// Block reductions (256 threads)
// ---------------------------------------------------------------------------
template<bool IS_MAX>
__device__ __forceinline__ float blockReduce(float v)
{
    __shared__ float sh[8];
    int lane = threadIdx.x & 31, w = threadIdx.x >> 5;
    #pragma unroll
    for (int o=16;o;o>>=1) {
        float u = __shfl_xor_sync(0xffffffffu, v, o);
        v = IS_MAX ? fmaxf(v,u) : v+u;
    }
    if (lane==0) sh[w] = v;
    __syncthreads();
    if (w==0) {
        v = (lane < 8) ? sh[lane] : (IS_MAX ? -__int_as_float(0x7f800000) : 0.f);
        #pragma unroll
        for (int o=4;o;o>>=1) {
            float u = __shfl_xor_sync(0xffffffffu, v, o);
            v = IS_MAX ? fmaxf(v,u) : v+u;
        }
        if (lane==0) sh[0] = v;
    }
    __syncthreads();
    float r = sh[0];
    __syncthreads();
    return r;
}

// ---------------------------------------------------------------------------
// Single-pass softmax: row of T=1024 in registers (float4/thread).
// Causal: touches only columns < ((t>>7)+1)*128 — exactly what causal PV reads.
// ---------------------------------------------------------------------------
__global__ __launch_bounds__(256)
void softmax_k(float* __restrict__ s, int causal)
{
    long row = blockIdx.x;
    int t = (int)(row % TT);
    float4* p = (float4*)(s + row * (long)TT);
    int tid = threadIdx.x;
    int base = 4*tid;
    int n  = causal ? (t+1) : TT;                       // valid width
    int nw = causal ? (((t>>7)+1)<<7) : TT;             // touched width
    const float NEG = -__int_as_float(0x7f800000);
    bool act = (base < nw);

    float4 v = act ? p[tid] : make_float4(NEG,NEG,NEG,NEG);
    if (base+0 >= n) v.x = NEG;
    if (base+1 >= n) v.y = NEG;
    if (base+2 >= n) v.z = NEG;
    if (base+3 >= n) v.w = NEG;

    float mx = fmaxf(fmaxf(v.x,v.y), fmaxf(v.z,v.w));
    mx = blockReduce<true>(mx);

    float4 e;
    e.x = __expf(v.x - mx); e.y = __expf(v.y - mx);
    e.z = __expf(v.z - mx); e.w = __expf(v.w - mx);
    float sum = (e.x + e.y) + (e.z + e.w);
    sum = blockReduce<false>(sum);
    float inv = 1.f / sum;
    e.x *= inv; e.y *= inv; e.z *= inv; e.w *= inv;
    if (act) p[tid] = e;
}

// ---------------------------------------------------------------------------
// LayerNorm: rows of C=512
// ---------------------------------------------------------------------------
__global__ __launch_bounds__(256)
void ln_k(const float* __restrict__ x, float* __restrict__ out,
          const float* __restrict__ gamma, const float* __restrict__ beta)
{
    long row = blockIdx.x;
    const float* xr = x + row*(long)CC;
    int tid = threadIdx.x;
    float v0 = xr[tid], v1 = xr[tid+256];
    float mu = blockReduce<false>(v0+v1) * (1.f/CC);
    float d0 = v0-mu, d1 = v1-mu;
    float var = blockReduce<false>(d0*d0 + d1*d1) * (1.f/CC);
    float inv = rsqrtf(var + 1e-5f);
    out[row*(long)CC + tid      ] = d0*inv*gamma[tid]     + beta[tid];
    out[row*(long)CC + tid + 256] = d1*inv*gamma[tid+256] + beta[tid+256];
}

// ---------------------------------------------------------------------------
// Embedding + positional encoding
// ---------------------------------------------------------------------------
__global__ __launch_bounds__(256)
void embed_k(const int* __restrict__ tok, const float* __restrict__ emb,
             float* __restrict__ out)
{
    long idx = (long)blockIdx.x*256 + threadIdx.x;
    if (idx >= (long)BB*TT*CC) return;
    int c = (int)(idx % CC);
    long bt = idx / CC;
    int t = (int)(bt % TT);
    int token = tok[bt];
    const int half = CC/2;
    float pe;
    if (c < half) {
        float rate = powf(10000.f, -(float)c / half);
        pe = sinf((float)t * rate);
    } else {
        float rate = powf(10000.f, -(float)(c-half) / half);
        pe = cosf((float)t * rate);
    }
    out[idx] = emb[(long)token*CC + c] * 22.62741699796952f + pe;  // sqrt(512)
}

// ---------------------------------------------------------------------------
// Host-side launchers
// ---------------------------------------------------------------------------
#define GEMM_D0  mma_gemm<128,64,32,32,32,false,0,0,0,0>   // dense fp32 in/out
#define GEMM_QKV mma_gemm<128,64,32,32,32,false,0,0,0,2>   // emit QKV planes
#define GEMM_T0  mma_gemm<128,64,32,32,32,true ,0,1,1,0>   // QK dense (planes in)
#define GEMM_T1  mma_gemm<128,64,32,32,32,true ,1,1,1,0>   // QK causal
#define GEMM_V0  mma_gemm<128,64,32,32,32,false,0,0,1,0>   // PV dense (V planes)
#define GEMM_V2  mma_gemm<128,64,32,32,32,false,2,0,1,0>   // PV causal

static void setAttrs()
{
    int sb = smemBytes<128,64,32>();
    cudaFuncSetAttribute((const void*)GEMM_D0,  cudaFuncAttributeMaxDynamicSharedMemorySize, sb);
    cudaFuncSetAttribute((const void*)GEMM_QKV, cudaFuncAttributeMaxDynamicSharedMemorySize, sb);
    cudaFuncSetAttribute((const void*)GEMM_T0,  cudaFuncAttributeMaxDynamicSharedMemorySize, sb);
    cudaFuncSetAttribute((const void*)GEMM_T1,  cudaFuncAttributeMaxDynamicSharedMemorySize, sb);
    cudaFuncSetAttribute((const void*)GEMM_V0,  cudaFuncAttributeMaxDynamicSharedMemorySize, sb);
    cudaFuncSetAttribute((const void*)GEMM_V2,  cudaFuncAttributeMaxDynamicSharedMemorySize, sb);
}

static void gemmP(const float* A, const float* B, float* C,
                  const float* bias, const float* resid,
                  int M, int N, int K, int relu)
{
    dim3 g(N/64, M/128, 1);
    GEMM_D0<<<g,256,smemBytes<128,64,32>()>>>(
        A, A, B, C, nullptr, 0, 0, 0, bias, resid, K, K, N, N,
        1,1, 0,0,0, 0,0,0, 0,0,0, 0,0,0, 1.f, relu);
}

// Full multi-head attention; att gets head-concat output [B*T, C].
static void attention(const float* xq, const float* xkv,
                      const float* wqkv, const float* bqkv,
                      __nv_bfloat16* qkvp, float* s, float* att, float* cdummy,
                      int causal)
{
    const int sb = smemBytes<128,64,32>();
    const long PO = (long)3*QSZ;    // plane offset (elements)
    // Fused QKV projection: z = j*16 + b*8 + h; emits bf16 planes only
    {
        dim3 g(1, TT/128, 48);
        GEMM_QKV<<<g,256,sb>>>(
            xq, xkv, wqkv, cdummy, qkvp, 0, 0, PO,
            bqkv, nullptr,
            CC, CC, DD, DD,
            16, 8,
            0, (long)TT*CC, 0,
            (long)HH*CC*DD, 0, (long)CC*DD,
            (long)QSZ, (long)HH*TT*DD, (long)TT*DD,
            (long)HH*DD, 0, (long)DD,
            1.f, 0);
    }
    // scores = Q @ K^T * sqrt(D)   (z = b*H+h); Q/K from planes
    {
        dim3 g(TT/64, TT/128, BH);
        const float* Qp = (const float*)qkvp;
        const float* Kp = (const float*)(qkvp + QSZ);
        if (causal)
            GEMM_T1<<<g,256,sb>>>(
                Qp, Qp, Kp, s, nullptr, PO, PO, 0, nullptr, nullptr,
                DD, DD, DD, TT,
                1000000, 1,
                0, (long)TT*DD, 0,
                0, (long)TT*DD, 0,
                0, (long)TT*TT, 0,
                0,0,0,
                8.0f, 0);
        else
            GEMM_T0<<<g,256,sb>>>(
                Qp, Qp, Kp, s, nullptr, PO, PO, 0, nullptr, nullptr,
                DD, DD, DD, TT,
                1000000, 1,
                0, (long)TT*DD, 0,
                0, (long)TT*DD, 0,
                0, (long)TT*TT, 0,
                0,0,0,
                8.0f, 0);
    }
    softmax_k<<<BH*TT, 256>>>(s, causal);
    // out = P @ V; V from planes; head-concat epilogue (ldc=C, col offset h*D)
    {
        dim3 g(1, TT/128, BH);
        const float* Vp = (const float*)(qkvp + 2*QSZ);
        if (causal)
            GEMM_V2<<<g,256,sb>>>(
                s, s, Vp, att, nullptr, 0, PO, 0, nullptr, nullptr,
                TT, TT, DD, CC,
                1000000, HH,
                0, (long)HH*TT*TT, (long)TT*TT,
                0, (long)HH*TT*DD, (long)TT*DD,
                0, (long)TT*CC, (long)DD,
                0,0,0,
                1.f, 0);
        else
            GEMM_V0<<<g,256,sb>>>(
                s, s, Vp, att, nullptr, 0, PO, 0, nullptr, nullptr,
                TT, TT, DD, CC,
                1000000, HH,
                0, (long)HH*TT*TT, (long)TT*TT,
                0, (long)HH*TT*DD, (long)TT*DD,
                0, (long)TT*CC, (long)DD,
                0,0,0,
                1.f, 0);
    }
}

extern "C" void kernel_launch(void* const* d_in, const int* in_sizes, int n_in,
                              void* d_out, int out_size)
{
    const int*   src     = (const int*)  d_in[0];
    const int*   tgt     = (const int*)  d_in[1];
    const float* src_emb = (const float*)d_in[2];
    const float* tgt_emb = (const float*)d_in[3];
    const float* e_wqkv  = (const float*)d_in[4];
    const float* e_bqkv  = (const float*)d_in[5];
    const float* e_wo    = (const float*)d_in[6];
    const float* e_bo    = (const float*)d_in[7];
    const float* e_ln1   = (const float*)d_in[8];
    const float* e_ln2   = (const float*)d_in[9];
    const float* e_fw1   = (const float*)d_in[10];
    const float* e_fb1   = (const float*)d_in[11];
    const float* e_fw2   = (const float*)d_in[12];
    const float* e_fb2   = (const float*)d_in[13];
    const float* dsw     = (const float*)d_in[14];
    const float* dsb     = (const float*)d_in[15];
    const float* dw1     = (const float*)d_in[16];
    const float* db1     = (const float*)d_in[17];
    const float* dln1    = (const float*)d_in[18];
    const float* dcw     = (const float*)d_in[19];
    const float* dcb     = (const float*)d_in[20];
    const float* dw2     = (const float*)d_in[21];
    const float* db2     = (const float*)d_in[22];
    const float* dln2    = (const float*)d_in[23];
    const float* dln3    = (const float*)d_in[24];
    const float* dfw1    = (const float*)d_in[25];
    const float* dfb1    = (const float*)d_in[26];
    const float* dfw2    = (const float*)d_in[27];
    const float* dfb2    = (const float*)d_in[28];
    const float* wf      = (const float*)d_in[29];
    const float* bf      = (const float*)d_in[30];
    float* out = (float*)d_out;

    setAttrs();

    float *gx,*gy,*gl,*gs,*ga,*gf;
    __nv_bfloat16 *gqp;
    cudaGetSymbolAddress((void**)&gx, g_enc);
    cudaGetSymbolAddress((void**)&gy, g_dec);
    cudaGetSymbolAddress((void**)&gl, g_ln);
    cudaGetSymbolAddress((void**)&gs, g_s);
    cudaGetSymbolAddress((void**)&ga, g_att);
    cudaGetSymbolAddress((void**)&gf, g_ffn);
    cudaGetSymbolAddress((void**)&gqp, g_qkvp);

    const int embBlocks = (int)(((long)BB*TT*CC + 255) / 256);

    // ---------------- Encoder ----------------
    embed_k<<<embBlocks,256>>>(src, src_emb, gx);
    for (int l=0; l<LL; l++) {
        const float* ln1g = e_ln1 + (long)l*2*CC;
        ln_k<<<M2,256>>>(gx, gl, ln1g, ln1g + CC);
        attention(gl, gl,
                  e_wqkv + (long)l*3*HH*CC*DD, e_bqkv + (long)l*3*HH*DD,
                  gqp, gs, ga, gf, 0);
        gemmP(ga, e_wo + (long)l*CC*CC, gx, e_bo + (long)l*CC, gx, M2, CC, CC, 0);
        const float* ln2g = e_ln2 + (long)l*2*CC;
        ln_k<<<M2,256>>>(gx, gl, ln2g, ln2g + CC);
        gemmP(gl, e_fw1 + (long)l*CC*FF, gf, e_fb1 + (long)l*FF, nullptr, M2, FF, CC, 1);
        gemmP(gf, e_fw2 + (long)l*FF*CC, gx, e_fb2 + (long)l*CC, gx, M2, CC, FF, 0);
    }

    // ---------------- Decoder ----------------
    embed_k<<<embBlocks,256>>>(tgt, tgt_emb, gy);
    for (int l=0; l<LL; l++) {
        const float* l1 = dln1 + (long)l*2*CC;
        ln_k<<<M2,256>>>(gy, gl, l1, l1 + CC);
        attention(gl, gl,
                  dsw + (long)l*3*HH*CC*DD, dsb + (long)l*3*HH*DD,
                  gqp, gs, ga, gf, 1);                 // causal
        gemmP(ga, dw1 + (long)l*CC*CC, gy, db1 + (long)l*CC, gy, M2, CC, CC, 0);
        const float* l2 = dln2 + (long)l*2*CC;
        ln_k<<<M2,256>>>(gy, gl, l2, l2 + CC);
        attention(gl, gx,                              // cross: kv = enc_out
                  dcw + (long)l*3*HH*CC*DD, dcb + (long)l*3*HH*DD,
                  gqp, gs, ga, gf, 0);
        gemmP(ga, dw2 + (long)l*CC*CC, gy, db2 + (long)l*CC, gy, M2, CC, CC, 0);
        const float* l3 = dln3 + (long)l*2*CC;
        ln_k<<<M2,256>>>(gy, gl, l3, l3 + CC);
        gemmP(gl, dfw1 + (long)l*CC*FF, gf, dfb1 + (long)l*FF, nullptr, M2, FF, CC, 1);
        gemmP(gf, dfw2 + (long)l*FF*CC, gy, dfb2 + (long)l*CC, gy, M2, CC, FF, 0);
    }

    // ---------------- Final logits ----------------
    gemmP(gy, wf, out, bf, nullptr, M2, VV, CC, 0);
}

// round 14
// speedup vs baseline: 1.0654x; 1.0171x over previous
#include <cuda_runtime.h>
#include <cuda_bf16.h>
#include <math.h>
#include <stdint.h>

// Problem constants
#define LL 6
#define HH 8
#define CC 512
#define DD 64
#define FF 2048
#define VV 32000
#define BB 2
#define TT 1024
#define M2 (BB*TT)          // 2048 token rows
#define BH (BB*HH)          // 16 attention batches
#define QSZ (BH*TT*DD)      // one of Q/K/V

// ---------------------------------------------------------------------------
// Scratch (static device globals — allocation-free per harness rules)
// ---------------------------------------------------------------------------
__device__ float g_enc[M2*CC];
__device__ float g_dec[M2*CC];
__device__ float g_ln [M2*CC];
__device__ float g_s  [(long)BH*TT*TT];  // attention scores (64 MB)
__device__ float g_att[M2*CC];
__device__ float g_ffn[M2*FF];
// QKV bf16 hi/lo planes: [hi: j,b,h,T,D][lo: same], lo at +3*QSZ elements
__device__ __align__(16) __nv_bfloat16 g_qkvp[2*3*QSZ];

// ---------------------------------------------------------------------------
// bf16x2 double-bf16 helpers: v = hi + lo. 3 bf16 MMAs ~ fp32-ish.
// ---------------------------------------------------------------------------
__device__ __forceinline__ uint32_t pk(float k0, float k1){
    // pack: low half = bf16(k0), high half = bf16(k1)
    uint32_t r; asm("cvt.rn.bf16x2.f32 %0, %1, %2;" : "=r"(r) : "f"(k1), "f"(k0));
    return r;
}
__device__ __forceinline__ float lowf (uint32_t u){ return __uint_as_float(u << 16); }
__device__ __forceinline__ float highf(uint32_t u){ return __uint_as_float(u & 0xffff0000u); }
__device__ __forceinline__ void split4(const float4& v, uint2& hi, uint2& lo){
    uint32_t h0 = pk(v.x, v.y), h1 = pk(v.z, v.w);
    lo = make_uint2(pk(v.x-lowf(h0), v.y-highf(h0)), pk(v.z-lowf(h1), v.w-highf(h1)));
    hi = make_uint2(h0, h1);
}
__device__ __forceinline__ void mma16(float* c, const uint32_t* a, const uint32_t* b){
    asm volatile("mma.sync.aligned.m16n8k16.row.col.f32.bf16.bf16.f32 "
        "{%0,%1,%2,%3},{%4,%5,%6,%7},{%8,%9},{%0,%1,%2,%3};"
        : "+f"(c[0]),"+f"(c[1]),"+f"(c[2]),"+f"(c[3])
        : "r"(a[0]),"r"(a[1]),"r"(a[2]),"r"(a[3]),"r"(b[0]),"r"(b[1]));
}
__device__ __forceinline__ void ldsm4(uint32_t* r, uint32_t addr){
    asm volatile("ldmatrix.sync.aligned.m8n8.x4.shared.b16 {%0,%1,%2,%3}, [%4];"
        : "=r"(r[0]),"=r"(r[1]),"=r"(r[2]),"=r"(r[3]) : "r"(addr));
}
__device__ __forceinline__ void ldsm4t(uint32_t* r, uint32_t addr){
    asm volatile("ldmatrix.sync.aligned.m8n8.x4.trans.shared.b16 {%0,%1,%2,%3}, [%4];"
        : "=r"(r[0]),"=r"(r[1]),"=r"(r[2]),"=r"(r[3]) : "r"(addr));
}

// ---------------------------------------------------------------------------
// Generic batched bf16x2 GEMM, ldmatrix fragment loads, plane smem layout.
// Tile 128x64, BK=32, 8 warps (warp tile 32x32), 2 CTAs/SM.
// CMODE: 0=dense, 1=causal-QK (skip masked tiles), 2=causal-PV (K truncate)
// ASRC:  0=A fp32 (split at STS), 1=A pre-split bf16 planes (pure copy)
// BSRC:  0=B fp32 (split at STS), 1=B pre-split bf16 planes (pure copy)
// EMIT:  0=write fp32 C, 2=write bf16 hi/lo planes ONLY (no fp32)
// TRANSB && BSRC==1: B kept in native [n][k] layout (stride BK+8, 16B-aligned),
//                    non-trans ldsm B-frags.
// ---------------------------------------------------------------------------
template<int BM,int BN,int BK,int WM,int WN,bool TRANSB,int CMODE,int ASRC,int BSRC,int EMIT>
__global__ __launch_bounds__(256,2)
void mma_gemm(const float* __restrict__ A, const float* __restrict__ A2,
              const float* __restrict__ B, float* __restrict__ C,
              __nv_bfloat16* __restrict__ Ehi, long aPOff, long bPOff, long ePOff,
              const float* __restrict__ bias, const float* __restrict__ resid,
              int K, int lda, int ldb, int ldc,
              int zDiv1, int zDiv2,
              long aS0, long aS1, long aS2,
              long bS0, long bS1, long bS2,
              long cS0, long cS1, long cS2,
              long sS0, long sS1, long sS2,
              float alpha, int relu)
{
    constexpr bool BNK = (TRANSB && BSRC==1);   // B native [n][k] layout
    constexpr int BKA = BK + 8;                 // A plane row stride (elems): 80B
    constexpr int BKB = BK + 8;                 // B [n][k] row stride (elems): 80B (16B-aligned)
    constexpr int BNB = BN + 8;                 // B [k][n] row stride (elems)
    constexpr int A_PLANE = BM*BKA*2;           // bytes
    constexpr int A_BUF   = 2*A_PLANE;
    constexpr int B_PLANE = BNK ? BN*BKB*2 : BK*BNB*2;
    constexpr int B_BUF   = 2*B_PLANE;
    constexpr int BUF     = A_BUF + B_BUF;
    constexpr int WCOLS = BN / WN;
    constexpr int MITER = WM/16, NITER = WN/8;
    constexpr int AREG = BM*BK/(256*4);

    const int row0 = blockIdx.y * BM;
    const int col0 = blockIdx.x * BN;
    if (CMODE == 1 && col0 > row0 + BM - 1) return;   // fully-masked causal tile
    const int Keff = (CMODE == 2) ? min(K, row0 + BM) : K;

    extern __shared__ char smem[];
    const uint32_t sbase = (uint32_t)__cvta_generic_to_shared(smem);

    const int z = blockIdx.z;
    const int i0 = z / zDiv1, rem = z % zDiv1;
    const int i1 = rem / zDiv2, i2 = rem % zDiv2;
    const float* Asel = (i0==0) ? A : A2;
    const float* Ap = nullptr;
    const __nv_bfloat16* Ahp = nullptr;
    if (ASRC == 0) Ap  = Asel + i0*aS0 + i1*aS1 + i2*aS2;
    else           Ahp = reinterpret_cast<const __nv_bfloat16*>(Asel) + i0*aS0 + i1*aS1 + i2*aS2;
    const float* Bp = nullptr;
    const __nv_bfloat16* Bhp = nullptr;
    if (BSRC == 0) Bp  = B + i0*bS0 + i1*bS1 + i2*bS2;
    else           Bhp = reinterpret_cast<const __nv_bfloat16*>(B) + i0*bS0 + i1*bS1 + i2*bS2;
    const long cOff = i0*cS0 + i1*cS1 + i2*cS2;
    float* Cp = C + cOff;
    const float* Rp = resid ? resid + cOff : nullptr;
    const float* bp = bias ? bias + i0*sS0 + i1*sS1 + i2*sS2 : nullptr;
    __nv_bfloat16* Ep = (EMIT==2) ? (Ehi + cOff) : nullptr;

    const int tid  = threadIdx.x;
    const int lane = tid & 31, w = tid >> 5;
    const int wr = w / WCOLS, wc = w % WCOLS;
    const int g  = lane >> 2, cq = lane & 3;

    const int aRow = (lane & 7) + ((lane >> 3) & 1) * 8;
    const int aCol = (lane >> 4) * 8;
    const uint32_t aOffB = ((wr*WM + aRow)*BKA + aCol) * 2;
    // B-frag addressing: trans path ([k][n]) vs native [n][k] path
    const int bRow = lane & 15;
    const int bColOff = (lane >> 4) * 8;
    const int nkRow = (lane & 7) + (lane >> 4) * 8;    // n within 16-group
    const int nkCol = ((lane >> 3) & 1) * 8;           // k offset
    const uint32_t bOffB = BNK
        ? ((wc*WN + nkRow)*BKB + nkCol) * 2
        : (bRow*BNB + wc*WN + bColOff) * 2;

    float acc[MITER][NITER][4];
    #pragma unroll
    for (int mi=0;mi<MITER;mi++)
        #pragma unroll
        for (int ni=0;ni<NITER;ni++)
            #pragma unroll
            for (int q=0;q<4;q++) acc[mi][ni][q] = 0.f;

    float4 ra[ASRC==0 ? AREG : 1];
    uint4  ra4[ASRC==1 ? 4 : 1];
    float4 rb[BSRC==0 ? 2 : 1];
    uint4  rb4[BSRC==1 ? 2 : 1];

    auto ldgA = [&](int k0){
        if (ASRC == 0){
            #pragma unroll
            for (int i=0;i<AREG;i++){
                int id = tid + i*256;
                int r = id >> 3, c4 = id & 7;
                ra[i] = *(const float4*)(Ap + (long)(row0+r)*lda + k0 + c4*4);
            }
        } else {
            #pragma unroll
            for (int i=0;i<2;i++){
                int id = tid + i*256;              // 0..511
                int r = id >> 2, c8 = (id & 3)*8;
                const __nv_bfloat16* hp = Ahp + (long)(row0+r)*lda + k0 + c8;
                ra4[i]   = *(const uint4*)hp;
                ra4[2+i] = *(const uint4*)(hp + aPOff);
            }
        }
    };
    auto stsA = [&](int buf){
        char* base = smem + buf*BUF;
        if (ASRC == 0){
            #pragma unroll
            for (int i=0;i<AREG;i++){
                int id = tid + i*256;
                int r = id >> 3, c4 = id & 7;
                uint2 hi, lo; split4(ra[i], hi, lo);
                int off = (r*BKA + c4*4)*2;
                *(uint2*)(base + off)           = hi;
                *(uint2*)(base + A_PLANE + off) = lo;
            }
        } else {
            #pragma unroll
            for (int i=0;i<2;i++){
                int id = tid + i*256;
                int r = id >> 2, c8 = (id & 3)*8;
                int off = (r*BKA + c8)*2;
                *(uint4*)(base + off)           = ra4[i];
                *(uint4*)(base + A_PLANE + off) = ra4[2+i];
            }
        }
    };
    auto ldgB = [&](int k0){
        if (BSRC == 0){
            #pragma unroll
            for (int j=0;j<2;j++){
                int id = tid + j*256;
                if (!TRANSB){
                    int r = id >> 4, n4 = id & 15;
                    rb[j] = *(const float4*)(Bp + (long)(k0+r)*ldb + col0 + n4*4);
                } else {
                    int n = id >> 3, kg = id & 7;
                    rb[j] = *(const float4*)(Bp + (long)(col0+n)*ldb + k0 + kg*4);
                }
            }
        } else {
            if (!TRANSB){
                int r = tid >> 3, n8 = (tid & 7)*8;
                const __nv_bfloat16* hp = Bhp + (long)(k0+r)*ldb + col0 + n8;
                rb4[0] = *(const uint4*)hp;
                rb4[1] = *(const uint4*)(hp + bPOff);
            } else {
                int n = tid >> 2, kg = (tid & 3)*8;
                const __nv_bfloat16* hp = Bhp + (long)(col0+n)*ldb + k0 + kg;
                rb4[0] = *(const uint4*)hp;
                rb4[1] = *(const uint4*)(hp + bPOff);
            }
        }
    };
    auto stsB = [&](int buf){
        char* base = smem + buf*BUF + A_BUF;
        if (BSRC == 0){
            #pragma unroll
            for (int j=0;j<2;j++){
                int id = tid + j*256;
                if (!TRANSB){
                    int r = id >> 4, n4 = id & 15;
                    uint2 hi, lo; split4(rb[j], hi, lo);
                    int off = (r*BNB + n4*4)*2;
                    *(uint2*)(base + off)           = hi;
                    *(uint2*)(base + B_PLANE + off) = lo;
                } else {
                    int n = id >> 3, kg = id & 7;
                    float v[4] = {rb[j].x, rb[j].y, rb[j].z, rb[j].w};
                    #pragma unroll
                    for (int e=0;e<4;e++){
                        int k = kg*4 + e;
                        uint32_t h = pk(v[e], 0.f);
                        float hf = __uint_as_float(h << 16);
                        uint32_t l = pk(v[e]-hf, 0.f);
                        int off = (k*BNB + n)*2;
                        *(uint16_t*)(base + off)           = (uint16_t)h;
                        *(uint16_t*)(base + B_PLANE + off) = (uint16_t)l;
                    }
                }
            }
        } else {
            if (!TRANSB){
                int r = tid >> 3, n8 = (tid & 7)*8;
                int off = (r*BNB + n8)*2;
                *(uint4*)(base + off)           = rb4[0];
                *(uint4*)(base + B_PLANE + off) = rb4[1];
            } else {
                // native [n][k] layout: pure 16B copies (stride 80B, aligned)
                int n = tid >> 2, kg = (tid & 3)*8;
                int off = (n*BKB + kg)*2;
                *(uint4*)(base + off)           = rb4[0];
                *(uint4*)(base + B_PLANE + off) = rb4[1];
            }
        }
    };
    auto compute = [&](int buf){
        const uint32_t aAddr = sbase + buf*BUF + aOffB;
        const uint32_t bAddr = sbase + buf*BUF + A_BUF + bOffB;
        #pragma unroll
        for (int s=0; s<BK/16; s++){
            uint32_t ah[MITER][4], al[MITER][4];
            #pragma unroll
            for (int mi=0; mi<MITER; mi++){
                uint32_t a = aAddr + (mi*16*BKA + s*16)*2;
                ldsm4(ah[mi], a);
                ldsm4(al[mi], a + A_PLANE);
            }
            uint32_t bh[2][4], bl[2][4];
            #pragma unroll
            for (int np=0; np<NITER/2; np++){
                if (BNK){
                    uint32_t b = bAddr + (np*16*BKB + s*16)*2;
                    ldsm4(bh[np], b);
                    ldsm4(bl[np], b + B_PLANE);
                } else {
                    uint32_t b = bAddr + (s*16*BNB + np*16)*2;
                    ldsm4t(bh[np], b);
                    ldsm4t(bl[np], b + B_PLANE);
                }
            }
            // term-outer: per-acc term order preserved (bit-identical),
            // dependent same-acc MMAs spaced MITER*NITER apart.
            #pragma unroll
            for (int mi=0; mi<MITER; mi++)
                #pragma unroll
                for (int ni=0; ni<NITER; ni++)
                    mma16(acc[mi][ni], al[mi], &bh[ni>>1][(ni&1)*2]);
            #pragma unroll
            for (int mi=0; mi<MITER; mi++)
                #pragma unroll
                for (int ni=0; ni<NITER; ni++)
                    mma16(acc[mi][ni], ah[mi], &bl[ni>>1][(ni&1)*2]);
            #pragma unroll
            for (int mi=0; mi<MITER; mi++)
                #pragma unroll
                for (int ni=0; ni<NITER; ni++)
                    mma16(acc[mi][ni], ah[mi], &bh[ni>>1][(ni&1)*2]);
        }
    };

    const int nIter = Keff/BK;
    ldgA(0); ldgB(0);
    stsA(0); stsB(0);
    __syncthreads();
    for (int it=0; it<nIter; ++it){
        if (it+1 < nIter){ ldgA((it+1)*BK); ldgB((it+1)*BK); }
        compute(it & 1);
        if (it+1 < nIter){ stsA((it+1)&1); stsB((it+1)&1); }
        __syncthreads();
    }

    #pragma unroll
    for (int mi=0;mi<MITER;mi++){
        #pragma unroll
        for (int ni=0;ni<NITER;ni++){
            int r  = row0 + wr*WM + mi*16 + g;
            int cl = col0 + wc*WN + ni*8 + 2*cq;
            #pragma unroll
            for (int h=0; h<2; h++){
                int rr = r + 8*h;
                float x = acc[mi][ni][2*h  ]*alpha;
                float y = acc[mi][ni][2*h+1]*alpha;
                if (bp){ x += bp[cl]; y += bp[cl+1]; }
                if (Rp){ float2 t = *(const float2*)(Rp + (long)rr*ldc + cl);
                         x += t.x; y += t.y; }
                if (relu){ x = fmaxf(x,0.f); y = fmaxf(y,0.f); }
                if (EMIT == 2){
                    uint32_t hh = pk(x,y);
                    uint32_t ll = pk(x-lowf(hh), y-highf(hh));
                    *(uint32_t*)(Ep + (long)rr*ldc + cl)         = hh;
                    *(uint32_t*)(Ep + ePOff + (long)rr*ldc + cl) = ll;
                } else {
                    *(float2*)(Cp + (long)rr*ldc + cl) = make_float2(x,y);
                }
            }
        }
    }
}

// smem bytes: [k][n] B layout (dense/non-trans paths)
template<int BM,int BN,int BK>
constexpr int smemBytes(){
    return 2 * ( 2*BM*(BK+8)*2 + 2*BK*(BN+8)*2 );
}
// smem bytes: native [n][k] B layout (BNK paths)
template<int BM,int BN,int BK>
constexpr int smemBytesBNK(){
    return 2 * ( 2*BM*(BK+8)*2 + 2*BN*(BK+8)*2 );
}

// ---------------------------------------------------------------------------
// Block reductions (256 threads)
// ---------------------------------------------------------------------------
template<bool IS_MAX>
__device__ __forceinline__ float blockReduce(float v)
{
    __shared__ float sh[8];
    int lane = threadIdx.x & 31, w = threadIdx.x >> 5;
    #pragma unroll
    for (int o=16;o;o>>=1) {
        float u = __shfl_xor_sync(0xffffffffu, v, o);
        v = IS_MAX ? fmaxf(v,u) : v+u;
    }
    if (lane==0) sh[w] = v;
    __syncthreads();
    if (w==0) {
        v = (lane < 8) ? sh[lane] : (IS_MAX ? -__int_as_float(0x7f800000) : 0.f);
        #pragma unroll
        for (int o=4;o;o>>=1) {
            float u = __shfl_xor_sync(0xffffffffu, v, o);
            v = IS_MAX ? fmaxf(v,u) : v+u;
        }
        if (lane==0) sh[0] = v;
    }
    __syncthreads();
    float r = sh[0];
    __syncthreads();
    return r;
}

// ---------------------------------------------------------------------------
// Single-pass softmax: row of T=1024 in registers (float4/thread).
// Causal: touches only columns < ((t>>7)+1)*128 — exactly what causal PV reads.
// ---------------------------------------------------------------------------
__global__ __launch_bounds__(256)
void softmax_k(float* __restrict__ s, int causal)
{
    long row = blockIdx.x;
    int t = (int)(row % TT);
    float4* p = (float4*)(s + row * (long)TT);
    int tid = threadIdx.x;
    int base = 4*tid;
    int n  = causal ? (t+1) : TT;                       // valid width
    int nw = causal ? (((t>>7)+1)<<7) : TT;             // touched width
    const float NEG = -__int_as_float(0x7f800000);
    bool act = (base < nw);

    float4 v = act ? p[tid] : make_float4(NEG,NEG,NEG,NEG);
    if (base+0 >= n) v.x = NEG;
    if (base+1 >= n) v.y = NEG;
    if (base+2 >= n) v.z = NEG;
    if (base+3 >= n) v.w = NEG;

    float mx = fmaxf(fmaxf(v.x,v.y), fmaxf(v.z,v.w));
    mx = blockReduce<true>(mx);

    float4 e;
    e.x = __expf(v.x - mx); e.y = __expf(v.y - mx);
    e.z = __expf(v.z - mx); e.w = __expf(v.w - mx);
    float sum = (e.x + e.y) + (e.z + e.w);
    sum = blockReduce<false>(sum);
    float inv = 1.f / sum;
    e.x *= inv; e.y *= inv; e.z *= inv; e.w *= inv;
    if (act) p[tid] = e;
}

// ---------------------------------------------------------------------------
// LayerNorm: rows of C=512
// ---------------------------------------------------------------------------
__global__ __launch_bounds__(256)
void ln_k(const float* __restrict__ x, float* __restrict__ out,
          const float* __restrict__ gamma, const float* __restrict__ beta)
{
    long row = blockIdx.x;
    const float* xr = x + row*(long)CC;
    int tid = threadIdx.x;
    float v0 = xr[tid], v1 = xr[tid+256];
    float mu = blockReduce<false>(v0+v1) * (1.f/CC);
    float d0 = v0-mu, d1 = v1-mu;
    float var = blockReduce<false>(d0*d0 + d1*d1) * (1.f/CC);
    float inv = rsqrtf(var + 1e-5f);
    out[row*(long)CC + tid      ] = d0*inv*gamma[tid]     + beta[tid];
    out[row*(long)CC + tid + 256] = d1*inv*gamma[tid+256] + beta[tid+256];
}

// ---------------------------------------------------------------------------
// Embedding + positional encoding
// ---------------------------------------------------------------------------
__global__ __launch_bounds__(256)
void embed_k(const int* __restrict__ tok, const float* __restrict__ emb,
             float* __restrict__ out)
{
    long idx = (long)blockIdx.x*256 + threadIdx.x;
    if (idx >= (long)BB*TT*CC) return;
    int c = (int)(idx % CC);
    long bt = idx / CC;
    int t = (int)(bt % TT);
    int token = tok[bt];
    const int half = CC/2;
    float pe;
    if (c < half) {
        float rate = powf(10000.f, -(float)c / half);
        pe = sinf((float)t * rate);
    } else {
        float rate = powf(10000.f, -(float)(c-half) / half);
        pe = cosf((float)t * rate);
    }
    out[idx] = emb[(long)token*CC + c] * 22.62741699796952f + pe;  // sqrt(512)
}

// ---------------------------------------------------------------------------
// Host-side launchers
// ---------------------------------------------------------------------------
#define GEMM_D0  mma_gemm<128,64,32,32,32,false,0,0,0,0>   // dense fp32 in/out
#define GEMM_QKV mma_gemm<128,64,32,32,32,false,0,0,0,2>   // emit QKV planes
#define GEMM_T0  mma_gemm<128,64,32,32,32,true ,0,1,1,0>   // QK dense (planes in)
#define GEMM_T1  mma_gemm<128,64,32,32,32,true ,1,1,1,0>   // QK causal
#define GEMM_V0  mma_gemm<128,64,32,32,32,false,0,0,1,0>   // PV dense (V planes)
#define GEMM_V2  mma_gemm<128,64,32,32,32,false,2,0,1,0>   // PV causal

static void setAttrs()
{
    int sb  = smemBytes<128,64,32>();
    int sbk = smemBytesBNK<128,64,32>();
    cudaFuncSetAttribute((const void*)GEMM_D0,  cudaFuncAttributeMaxDynamicSharedMemorySize, sb);
    cudaFuncSetAttribute((const void*)GEMM_QKV, cudaFuncAttributeMaxDynamicSharedMemorySize, sb);
    cudaFuncSetAttribute((const void*)GEMM_T0,  cudaFuncAttributeMaxDynamicSharedMemorySize, sbk);
    cudaFuncSetAttribute((const void*)GEMM_T1,  cudaFuncAttributeMaxDynamicSharedMemorySize, sbk);
    cudaFuncSetAttribute((const void*)GEMM_V0,  cudaFuncAttributeMaxDynamicSharedMemorySize, sb);
    cudaFuncSetAttribute((const void*)GEMM_V2,  cudaFuncAttributeMaxDynamicSharedMemorySize, sb);
}

static void gemmP(const float* A, const float* B, float* C,
                  const float* bias, const float* resid,
                  int M, int N, int K, int relu)
{
    dim3 g(N/64, M/128, 1);
    GEMM_D0<<<g,256,smemBytes<128,64,32>()>>>(
        A, A, B, C, nullptr, 0, 0, 0, bias, resid, K, K, N, N,
        1,1, 0,0,0, 0,0,0, 0,0,0, 0,0,0, 1.f, relu);
}

// Full multi-head attention; att gets head-concat output [B*T, C].
static void attention(const float* xq, const float* xkv,
                      const float* wqkv, const float* bqkv,
                      __nv_bfloat16* qkvp, float* s, float* att, float* cdummy,
                      int causal)
{
    const int sb  = smemBytes<128,64,32>();
    const int sbk = smemBytesBNK<128,64,32>();
    const long PO = (long)3*QSZ;    // plane offset (elements)
    // Fused QKV projection: z = j*16 + b*8 + h; emits bf16 planes only
    {
        dim3 g(1, TT/128, 48);
        GEMM_QKV<<<g,256,sb>>>(
            xq, xkv, wqkv, cdummy, qkvp, 0, 0, PO,
            bqkv, nullptr,
            CC, CC, DD, DD,
            16, 8,
            0, (long)TT*CC, 0,
            (long)HH*CC*DD, 0, (long)CC*DD,
            (long)QSZ, (long)HH*TT*DD, (long)TT*DD,
            (long)HH*DD, 0, (long)DD,
            1.f, 0);
    }
    // scores = Q @ K^T * sqrt(D)   (z = b*H+h); Q/K from planes
    {
        dim3 g(TT/64, TT/128, BH);
        const float* Qp = (const float*)qkvp;
        const float* Kp = (const float*)(qkvp + QSZ);
        if (causal)
            GEMM_T1<<<g,256,sbk>>>(
                Qp, Qp, Kp, s, nullptr, PO, PO, 0, nullptr, nullptr,
                DD, DD, DD, TT,
                1000000, 1,
                0, (long)TT*DD, 0,
                0, (long)TT*DD, 0,
                0, (long)TT*TT, 0,
                0,0,0,
                8.0f, 0);
        else
            GEMM_T0<<<g,256,sbk>>>(
                Qp, Qp, Kp, s, nullptr, PO, PO, 0, nullptr, nullptr,
                DD, DD, DD, TT,
                1000000, 1,
                0, (long)TT*DD, 0,
                0, (long)TT*DD, 0,
                0, (long)TT*TT, 0,
                0,0,0,
                8.0f, 0);
    }
    softmax_k<<<BH*TT, 256>>>(s, causal);
    // out = P @ V; V from planes; head-concat epilogue (ldc=C, col offset h*D)
    {
        dim3 g(1, TT/128, BH);
        const float* Vp = (const float*)(qkvp + 2*QSZ);
        if (causal)
            GEMM_V2<<<g,256,sb>>>(
                s, s, Vp, att, nullptr, 0, PO, 0, nullptr, nullptr,
                TT, TT, DD, CC,
                1000000, HH,
                0, (long)HH*TT*TT, (long)TT*TT,
                0, (long)HH*TT*DD, (long)TT*DD,
                0, (long)TT*CC, (long)DD,
                0,0,0,
                1.f, 0);
        else
            GEMM_V0<<<g,256,sb>>>(
                s, s, Vp, att, nullptr, 0, PO, 0, nullptr, nullptr,
                TT, TT, DD, CC,
                1000000, HH,
                0, (long)HH*TT*TT, (long)TT*TT,
                0, (long)HH*TT*DD, (long)TT*DD,
                0, (long)TT*CC, (long)DD,
                0,0,0,
                1.f, 0);
    }
}

extern "C" void kernel_launch(void* const* d_in, const int* in_sizes, int n_in,
                              void* d_out, int out_size)
{
    const int*   src     = (const int*)  d_in[0];
    const int*   tgt     = (const int*)  d_in[1];
    const float* src_emb = (const float*)d_in[2];
    const float* tgt_emb = (const float*)d_in[3];
    const float* e_wqkv  = (const float*)d_in[4];
    const float* e_bqkv  = (const float*)d_in[5];
    const float* e_wo    = (const float*)d_in[6];
    const float* e_bo    = (const float*)d_in[7];
    const float* e_ln1   = (const float*)d_in[8];
    const float* e_ln2   = (const float*)d_in[9];
    const float* e_fw1   = (const float*)d_in[10];
    const float* e_fb1   = (const float*)d_in[11];
    const float* e_fw2   = (const float*)d_in[12];
    const float* e_fb2   = (const float*)d_in[13];
    const float* dsw     = (const float*)d_in[14];
    const float* dsb     = (const float*)d_in[15];
    const float* dw1     = (const float*)d_in[16];
    const float* db1     = (const float*)d_in[17];
    const float* dln1    = (const float*)d_in[18];
    const float* dcw     = (const float*)d_in[19];
    const float* dcb     = (const float*)d_in[20];
    const float* dw2     = (const float*)d_in[21];
    const float* db2     = (const float*)d_in[22];
    const float* dln2    = (const float*)d_in[23];
    const float* dln3    = (const float*)d_in[24];
    const float* dfw1    = (const float*)d_in[25];
    const float* dfb1    = (const float*)d_in[26];
    const float* dfw2    = (const float*)d_in[27];
    const float* dfb2    = (const float*)d_in[28];
    const float* wf      = (const float*)d_in[29];
    const float* bf      = (const float*)d_in[30];
    float* out = (float*)d_out;

    setAttrs();

    float *gx,*gy,*gl,*gs,*ga,*gf;
    __nv_bfloat16 *gqp;
    cudaGetSymbolAddress((void**)&gx, g_enc);
    cudaGetSymbolAddress((void**)&gy, g_dec);
    cudaGetSymbolAddress((void**)&gl, g_ln);
    cudaGetSymbolAddress((void**)&gs, g_s);
    cudaGetSymbolAddress((void**)&ga, g_att);
    cudaGetSymbolAddress((void**)&gf, g_ffn);
    cudaGetSymbolAddress((void**)&gqp, g_qkvp);

    const int embBlocks = (int)(((long)BB*TT*CC + 255) / 256);

    // ---------------- Encoder ----------------
    embed_k<<<embBlocks,256>>>(src, src_emb, gx);
    for (int l=0; l<LL; l++) {
        const float* ln1g = e_ln1 + (long)l*2*CC;
        ln_k<<<M2,256>>>(gx, gl, ln1g, ln1g + CC);
        attention(gl, gl,
                  e_wqkv + (long)l*3*HH*CC*DD, e_bqkv + (long)l*3*HH*DD,
                  gqp, gs, ga, gf, 0);
        gemmP(ga, e_wo + (long)l*CC*CC, gx, e_bo + (long)l*CC, gx, M2, CC, CC, 0);
        const float* ln2g = e_ln2 + (long)l*2*CC;
        ln_k<<<M2,256>>>(gx, gl, ln2g, ln2g + CC);
        gemmP(gl, e_fw1 + (long)l*CC*FF, gf, e_fb1 + (long)l*FF, nullptr, M2, FF, CC, 1);
        gemmP(gf, e_fw2 + (long)l*FF*CC, gx, e_fb2 + (long)l*CC, gx, M2, CC, FF, 0);
    }

    // ---------------- Decoder ----------------
    embed_k<<<embBlocks,256>>>(tgt, tgt_emb, gy);
    for (int l=0; l<LL; l++) {
        const float* l1 = dln1 + (long)l*2*CC;
        ln_k<<<M2,256>>>(gy, gl, l1, l1 + CC);
        attention(gl, gl,
                  dsw + (long)l*3*HH*CC*DD, dsb + (long)l*3*HH*DD,
                  gqp, gs, ga, gf, 1);                 // causal
        gemmP(ga, dw1 + (long)l*CC*CC, gy, db1 + (long)l*CC, gy, M2, CC, CC, 0);
        const float* l2 = dln2 + (long)l*2*CC;
        ln_k<<<M2,256>>>(gy, gl, l2, l2 + CC);
        attention(gl, gx,                              // cross: kv = enc_out
                  dcw + (long)l*3*HH*CC*DD, dcb + (long)l*3*HH*DD,
                  gqp, gs, ga, gf, 0);
        gemmP(ga, dw2 + (long)l*CC*CC, gy, db2 + (long)l*CC, gy, M2, CC, CC, 0);
        const float* l3 = dln3 + (long)l*2*CC;
        ln_k<<<M2,256>>>(gy, gl, l3, l3 + CC);
        gemmP(gl, dfw1 + (long)l*CC*FF, gf, dfb1 + (long)l*FF, nullptr, M2, FF, CC, 1);
        gemmP(gf, dfw2 + (long)l*FF*CC, gy, dfb2 + (long)l*CC, gy, M2, CC, FF, 0);
    }

    // ---------------- Final logits ----------------
    gemmP(gy, wf, out, bf, nullptr, M2, VV, CC, 0);
}